// round 17
// baseline (speedup 1.0000x reference)
#include <cuda_runtime.h>

// Malvar-He-Cutler demosaic, GB300 (sm_103a). Round 17:
// Each warp walks 16 rows (8 pairs) of its 128-col band with a ROLLING 6-row
// register window: steady state loads only 2 new rows per 2 output rows
// (1 load-row/output-row vs 3), prefetched one pair ahead. Per-warp
// double-buffered smem slabs + cp.async.bulk stores kept one group in
// flight (wait_group.read 1) so store tails overlap the next pair.

__device__ __forceinline__ float clip01(float v) {
    return fminf(fmaxf(v, 0.0f), 1.0f);
}
__device__ __forceinline__ int refl(int i, int n) {
    i = (i < 0) ? -i : i;
    return (i >= n) ? (2 * n - 2 - i) : i;
}
__device__ __forceinline__ unsigned smem_u32(const void* p) {
    return (unsigned)__cvta_generic_to_shared(p);
}

#define ROW_FLOATS 384       // 128 px * 3 ch
#define ROW_BYTES  1536
#define PAIRS      8         // 16 rows per warp

__global__ void __launch_bounds__(256, 3)
demosaic_kernel(const float* __restrict__ x, float* __restrict__ out,
                int H, int W)
{
    __shared__ __align__(16) float s_out[8][2][2][ROW_FLOATS];  // 48 KB: [warp][buf][row01]

    const unsigned FM = 0xffffffffu;
    const int lane = threadIdx.x;                    // 0..31
    const int ty   = threadIdx.y;                    // 0..7 (= warp id)
    const int warp_c0 = blockIdx.x * 128;
    const int base_c  = warp_c0 + lane * 4;
    const int r_base  = (blockIdx.y * 8 + ty) * (2 * PAIRS);   // warp's first output row
    if (r_base >= H) return;

    const int bc_ld = (base_c + 4 <= W) ? base_c : (W - 4);
    const bool is_l = (lane == 0), is_r = (lane == 31);
    const int hcol = is_l ? (base_c - 2) : (base_c + 4);
    const bool hcol_ok = (hcol >= 0) & (hcol + 2 <= W);
    const int h0 = refl(hcol, W), h1 = refl(hcol + 1, W);

    // ---- preload 6-row window: rows r_base-2 .. r_base+3 ----
    float4 rv[6];
    float2 hv[6];
    if (r_base >= 2 && r_base + 3 < H) {
        const float* rp = x + (size_t)(r_base - 2) * W;
        #pragma unroll
        for (int j = 0; j < 6; ++j)
            rv[j] = *reinterpret_cast<const float4*>(rp + (size_t)j * W + bc_ld);
        if (is_l | is_r) {
            if (hcol_ok) {
                #pragma unroll
                for (int j = 0; j < 6; ++j)
                    hv[j] = *reinterpret_cast<const float2*>(rp + (size_t)j * W + hcol);
            } else {
                #pragma unroll
                for (int j = 0; j < 6; ++j) {
                    hv[j].x = rp[(size_t)j * W + h0];
                    hv[j].y = rp[(size_t)j * W + h1];
                }
            }
        }
    } else {
        #pragma unroll
        for (int j = 0; j < 6; ++j) {
            const int rr = refl(r_base - 2 + j, H);
            rv[j] = *reinterpret_cast<const float4*>(x + (size_t)rr * W + bc_ld);
            if (is_l | is_r) {
                hv[j].x = x[(size_t)rr * W + h0];
                hv[j].y = x[(size_t)rr * W + h1];
            }
        }
    }

    #pragma unroll 2
    for (int k = 0; k < PAIRS; ++k) {
        const int gr0 = r_base + 2 * k;
        const bool rows_ok = (gr0 + 2 <= H);

        // ---- prefetch next pair's 2 rows (hidden under this pair's compute) ----
        float4 t0, t1;
        float2 th0, th1;
        if (k < PAIRS - 1) {
            const int r4 = gr0 + 4, r5 = gr0 + 5;
            if (r5 < H) {
                const float* rp = x + (size_t)r4 * W;
                t0 = *reinterpret_cast<const float4*>(rp + bc_ld);
                t1 = *reinterpret_cast<const float4*>(rp + W + bc_ld);
                if (is_l | is_r) {
                    if (hcol_ok) {
                        th0 = *reinterpret_cast<const float2*>(rp + hcol);
                        th1 = *reinterpret_cast<const float2*>(rp + W + hcol);
                    } else {
                        th0.x = rp[h0];              th0.y = rp[h1];
                        th1.x = rp[(size_t)W + h0];  th1.y = rp[(size_t)W + h1];
                    }
                }
            } else {
                const int rr4 = refl(r4, H), rr5 = refl(r5, H);
                t0 = *reinterpret_cast<const float4*>(x + (size_t)rr4 * W + bc_ld);
                t1 = *reinterpret_cast<const float4*>(x + (size_t)rr5 * W + bc_ld);
                if (is_l | is_r) {
                    th0.x = x[(size_t)rr4 * W + h0]; th0.y = x[(size_t)rr4 * W + h1];
                    th1.x = x[(size_t)rr5 * W + h0]; th1.y = x[(size_t)rr5 * W + h1];
                }
            }
        }

        // ---- free the slab we're about to write (group k-2 read done) ----
        if (lane == 0)
            asm volatile("cp.async.bulk.wait_group.read 1;" ::: "memory");
        __syncwarp();

        // ---- bases from rolling window ----
        float ae[4], be[4], ce[4], ao[4], bo[4], co[4];
        {
            const float* r0 = (const float*)&rv[0];
            const float* r1 = (const float*)&rv[1];
            const float* r2 = (const float*)&rv[2];
            const float* r3 = (const float*)&rv[3];
            const float* r4p = (const float*)&rv[4];
            const float* r5p = (const float*)&rv[5];
            #pragma unroll
            for (int i = 0; i < 4; ++i) {
                ae[i] = r0[i] + r4p[i];
                be[i] = r1[i] + r3[i];
                ce[i] = r2[i];
                ao[i] = r1[i] + r5p[i];
                bo[i] = r2[i] + r4p[i];
                co[i] = r3[i];
            }
        }

        float hce0 = 0, hce1 = 0, hbe0 = 0, hbe1 = 0;
        float hco0 = 0, hco1 = 0, hbo0 = 0, hbo1 = 0;
        if (is_l | is_r) {
            hce0 = hv[2].x;            hce1 = hv[2].y;
            hbe0 = hv[1].x + hv[3].x;  hbe1 = hv[1].y + hv[3].y;
            hco0 = hv[3].x;            hco1 = hv[3].y;
            hbo0 = hv[2].x + hv[4].x;  hbo1 = hv[2].y + hv[4].y;
        }

        float le_c0 = __shfl_up_sync(FM, ce[2], 1);
        float le_c1 = __shfl_up_sync(FM, ce[3], 1);
        float le_b  = __shfl_up_sync(FM, be[3], 1);
        float lo_c0 = __shfl_up_sync(FM, co[2], 1);
        float lo_c1 = __shfl_up_sync(FM, co[3], 1);
        float lo_b  = __shfl_up_sync(FM, bo[3], 1);
        float re_c0 = __shfl_down_sync(FM, ce[0], 1);
        float re_c1 = __shfl_down_sync(FM, ce[1], 1);
        float re_b  = __shfl_down_sync(FM, be[0], 1);
        float ro_c0 = __shfl_down_sync(FM, co[0], 1);
        float ro_c1 = __shfl_down_sync(FM, co[1], 1);
        float ro_b  = __shfl_down_sync(FM, bo[0], 1);
        if (is_l) { le_c0 = hce0; le_c1 = hce1; le_b = hbe1;
                    lo_c0 = hco0; lo_c1 = hco1; lo_b = hbo1; }
        if (is_r) { re_c0 = hce0; re_c1 = hce1; re_b = hbe0;
                    ro_c0 = hco0; ro_c1 = hco1; ro_b = hbo0; }

        float* slab0 = &s_out[ty][k & 1][0][lane * 12];
        float* slab1 = &s_out[ty][k & 1][1][lane * 12];

        // Row 0 (even): R Gr R Gr
        {
            const float cx[8] = {le_c0, le_c1, ce[0], ce[1], ce[2], ce[3], re_c0, re_c1};
            const float bx[6] = {le_b,  be[0], be[1], be[2], be[3], re_b};
            float o[12];
            #pragma unroll
            for (int p = 0; p < 4; ++p) {
                const float cc = cx[p+2], bb = bx[p+1], aa = ae[p];
                const float s1v = cx[p+1] + cx[p+3];
                const float s2v = cx[p]   + cx[p+4];
                const float s3v = bx[p]   + bx[p+2];
                const float gi  = 0.125f * (4.0f*cc + 2.0f*(bb + s1v) - (aa + s2v));
                const float rgr = 0.125f * (5.0f*cc + 4.0f*s1v - s2v + 0.5f*aa - s3v);
                const float rgv = 0.125f * (5.0f*cc + 4.0f*bb - aa + 0.5f*s2v - s3v);
                const float rb  = 0.125f * (6.0f*cc + 2.0f*s3v - 1.5f*(aa + s2v));
                if ((p & 1) == 0) { o[3*p]=clip01(cc);  o[3*p+1]=clip01(gi); o[3*p+2]=clip01(rb);  }
                else              { o[3*p]=clip01(rgr); o[3*p+1]=clip01(cc); o[3*p+2]=clip01(rgv); }
            }
            float4* s4 = reinterpret_cast<float4*>(slab0);
            s4[0] = make_float4(o[0], o[1], o[2],  o[3]);
            s4[1] = make_float4(o[4], o[5], o[6],  o[7]);
            s4[2] = make_float4(o[8], o[9], o[10], o[11]);
        }
        // Row 1 (odd): Gb B Gb B
        {
            const float cx[8] = {lo_c0, lo_c1, co[0], co[1], co[2], co[3], ro_c0, ro_c1};
            const float bx[6] = {lo_b,  bo[0], bo[1], bo[2], bo[3], ro_b};
            float o[12];
            #pragma unroll
            for (int p = 0; p < 4; ++p) {
                const float cc = cx[p+2], bb = bx[p+1], aa = ao[p];
                const float s1v = cx[p+1] + cx[p+3];
                const float s2v = cx[p]   + cx[p+4];
                const float s3v = bx[p]   + bx[p+2];
                const float gi  = 0.125f * (4.0f*cc + 2.0f*(bb + s1v) - (aa + s2v));
                const float rgr = 0.125f * (5.0f*cc + 4.0f*s1v - s2v + 0.5f*aa - s3v);
                const float rgv = 0.125f * (5.0f*cc + 4.0f*bb - aa + 0.5f*s2v - s3v);
                const float rb  = 0.125f * (6.0f*cc + 2.0f*s3v - 1.5f*(aa + s2v));
                if ((p & 1) == 0) { o[3*p]=clip01(rgv); o[3*p+1]=clip01(cc); o[3*p+2]=clip01(rgr); }
                else              { o[3*p]=clip01(rb);  o[3*p+1]=clip01(gi); o[3*p+2]=clip01(cc);  }
            }
            float4* s4 = reinterpret_cast<float4*>(slab1);
            s4[0] = make_float4(o[0], o[1], o[2],  o[3]);
            s4[1] = make_float4(o[4], o[5], o[6],  o[7]);
            s4[2] = make_float4(o[8], o[9], o[10], o[11]);
        }

        __syncwarp();

        if ((warp_c0 + 128 <= W) && rows_ok) {
            if (lane == 0) {
                asm volatile("fence.proxy.async.shared::cta;" ::: "memory");
                float* dst0 = out + ((size_t)gr0 * W + warp_c0) * 3;
                float* dst1 = dst0 + (size_t)W * 3;
                const unsigned src0 = smem_u32(&s_out[ty][k & 1][0][0]);
                const unsigned src1 = smem_u32(&s_out[ty][k & 1][1][0]);
                asm volatile("cp.async.bulk.global.shared::cta.bulk_group [%0], [%1], %2;"
                             :: "l"(dst0), "r"(src0), "r"((unsigned)ROW_BYTES) : "memory");
                asm volatile("cp.async.bulk.global.shared::cta.bulk_group [%0], [%1], %2;"
                             :: "l"(dst1), "r"(src1), "r"((unsigned)ROW_BYTES) : "memory");
                asm volatile("cp.async.bulk.commit_group;" ::: "memory");
            }
        } else {
            #pragma unroll
            for (int rr = 0; rr < 2; ++rr) {
                const int gr = gr0 + rr;
                if (gr >= H) break;
                #pragma unroll
                for (int p = 0; p < 4; ++p) {
                    const int col = base_c + p;
                    if (col < W) {
                        float* q2 = out + ((size_t)gr * W + col) * 3;
                        q2[0] = s_out[ty][k & 1][rr][lane * 12 + 3 * p];
                        q2[1] = s_out[ty][k & 1][rr][lane * 12 + 3 * p + 1];
                        q2[2] = s_out[ty][k & 1][rr][lane * 12 + 3 * p + 2];
                    }
                }
            }
            if (lane == 0)   // keep group parity consistent: commit an empty group
                asm volatile("cp.async.bulk.commit_group;" ::: "memory");
        }

        // ---- roll window by 2 rows ----
        rv[0] = rv[2]; rv[1] = rv[3]; rv[2] = rv[4]; rv[3] = rv[5];
        rv[4] = t0;    rv[5] = t1;
        if (is_l | is_r) {
            hv[0] = hv[2]; hv[1] = hv[3]; hv[2] = hv[4]; hv[3] = hv[5];
            hv[4] = th0;   hv[5] = th1;
        }
    }

    if (lane == 0)
        asm volatile("cp.async.bulk.wait_group 0;" ::: "memory");
}

extern "C" void kernel_launch(void* const* d_in, const int* in_sizes, int n_in,
                              void* d_out, int out_size)
{
    const float* x = (const float*)d_in[0];
    long nx = in_sizes[0];
    if (n_in > 1 && in_sizes[1] > in_sizes[0]) {  // defensive: pick the big tensor as x
        x = (const float*)d_in[1];
        nx = in_sizes[1];
    }

    const int W = 6144;
    const int H = (int)(nx / W);

    // grid.x = 128-col bands (fast-varying, R15 orientation), grid.y = 128-row strips
    dim3 block(32, 8);
    dim3 grid((unsigned)((W + 127) / 128),
              (unsigned)((H + 2 * PAIRS * 8 - 1) / (2 * PAIRS * 8)));

    demosaic_kernel<<<grid, block>>>(x, (float*)d_out, H, W);
}